// round 9
// baseline (speedup 1.0000x reference)
#include <cuda_runtime.h>
#include <math.h>

// Shape fixed by reference: B=2, L=2048, H=16, E=64
#define B_  2
#define L_  2048
#define H_  16
#define E_  64
#define BH_ 32            // B*H chains
#define CH_ 64            // chunk length along s
#define NC_ 32            // chunks per chain
#define HE_ 1024          // H*E row stride in floats
#define NBLK (BH_ * NC_)  // 1024 blocks
#define NT_  512          // threads per block
#define NSUB 8            // sub-groups of 64 channels
#define RPS  8            // rows per sub

// Scratch (__device__ globals; no allocations allowed)
__device__ float g_E   [BH_ * L_];           // e-scores
__device__ float g_agg [NBLK * E_];          // per-chunk sum of e*V
__device__ float g_aggE[NBLK];               // per-chunk sum of e
__device__ float g_sub [NBLK * NSUB * E_];   // EXCLUSIVE cross-sub EV prefix

// ---------------- K1: e-scores + per-chunk aggregates + sub prefixes -------
__global__ __launch_bounds__(NT_, 4) void k_aggregate(
    const float* __restrict__ keys,
    const float* __restrict__ values,
    const float* __restrict__ w_score)
{
    __shared__ float sV[CH_ * E_];     // 16 KB V tile
    __shared__ float se[CH_];
    __shared__ float spEV[NSUB * E_];
    __shared__ float spE[NSUB];

    const int tid = threadIdx.x;
    const int blk = blockIdx.x;
    const int bh  = blk >> 5;          // / NC_
    const int c   = blk & 31;          // % NC_
    const int b   = bh >> 4;
    const int h   = bh & 15;
    const int base = ((b * L_ + c * CH_) * H_ + h) * E_;

    const int d   = tid & 63;
    const int sub = tid >> 6;          // 0..7
    const int r0  = sub * RPS;

    // e[row] = exp(0.125 * dot(K[row], w_k)); 8 threads per row
    {
        const int row = tid >> 3, q = tid & 7;
        const float4* kq = reinterpret_cast<const float4*>(
            keys + base + row * HE_ + q * 8);
        const float4* wq = reinterpret_cast<const float4*>(
            w_score + E_ + q * 8);
        float dot = 0.f;
        #pragma unroll
        for (int j = 0; j < 2; j++) {
            const float4 k4 = kq[j];
            const float4 w4 = wq[j];
            dot += k4.x * w4.x + k4.y * w4.y + k4.z * w4.z + k4.w * w4.w;
        }
        dot += __shfl_xor_sync(0xffffffffu, dot, 1);
        dot += __shfl_xor_sync(0xffffffffu, dot, 2);
        dot += __shfl_xor_sync(0xffffffffu, dot, 4);
        if (q == 0) {
            const float e = __expf(dot * 0.125f);
            se[row] = e;
            g_E[bh * L_ + c * CH_ + row] = e;
        }
    }

    // stage V tile (float4, coalesced; 2 per thread)
    {
        const float4* vg = reinterpret_cast<const float4*>(values + base);
        float4* sv4 = reinterpret_cast<float4*>(sV);
        #pragma unroll
        for (int i = 0; i < 2; i++) {
            const int idx = tid + i * NT_;
            sv4[idx] = vg[(idx >> 4) * (HE_ / 4) + (idx & 15)];
        }
    }
    __syncthreads();

    // per-sub partial aggregates over 8 rows
    {
        float sumE = 0.f, sumEV = 0.f;
        #pragma unroll
        for (int r = 0; r < RPS; r++) {
            const float e = se[r0 + r];
            sumE += e;
            sumEV = fmaf(e, sV[(r0 + r) * E_ + d], sumEV);
        }
        spEV[sub * E_ + d] = sumEV;
        if (d == 0) spE[sub] = sumE;
    }
    __syncthreads();

    // exclusive cross-sub prefix (per thread: sum lower subs from smem)
    {
        float exc = 0.f;
        #pragma unroll
        for (int s = 0; s < NSUB - 1; s++)
            if (s < sub) exc += spEV[s * E_ + d];
        g_sub[(blk * NSUB + sub) * E_ + d] = exc;
    }

    // block aggregate
    if (tid < E_) {
        float a = 0.f;
        #pragma unroll
        for (int s = 0; s < NSUB; s++) a += spEV[s * E_ + tid];
        g_agg[blk * E_ + tid] = a;
        if (tid == 0) {
            float ae = 0.f;
            #pragma unroll
            for (int s = 0; s < NSUB; s++) ae += spE[s];
            g_aggE[blk] = ae;
        }
    }
}

// ---------------- K2: prefix + output scan (divide-free, 8 rows/thread) ----
__global__ __launch_bounds__(NT_, 4) void k_output(
    const float* __restrict__ values,
    float* __restrict__ out)
{
    __shared__ float se[CH_];          // e-scores for this chunk
    __shared__ float srcp[CH_];        // 1 / cumulative-E per row
    __shared__ float sqEV[NSUB * E_];  // chunk-prefix partials

    const int tid = threadIdx.x;
    const int blk = blockIdx.x;
    const int bh  = blk >> 5;
    const int c   = blk & 31;
    const int b   = bh >> 4;
    const int h   = bh & 15;
    const int base = ((b * L_ + c * CH_) * H_ + h) * E_;

    const int d   = tid & 63;
    const int sub = tid >> 6;          // 0..7
    const int r0  = sub * RPS;

    // chunk-prefix EV loads, split 8 ways
    {
        float pEV = 0.f;
        for (int t = sub; t < c; t += NSUB)
            pEV += g_agg[(bh * NC_ + t) * E_ + d];
        sqEV[sub * E_ + d] = pEV;
    }

    // last warp: E-side. preE reduce + pair-scan + 2 reciprocals
    if (tid >= NT_ - 32) {
        const int lane = tid & 31;
        float pe = (lane < c) ? g_aggE[bh * NC_ + lane] : 0.f;
        #pragma unroll
        for (int o = 16; o; o >>= 1) pe += __shfl_xor_sync(0xffffffffu, pe, o);
        const float2 e2 = reinterpret_cast<const float2*>(
            g_E + bh * L_ + c * CH_)[lane];
        const float p = e2.x + e2.y;
        float incl = p;
        #pragma unroll
        for (int o = 1; o < 32; o <<= 1) {
            const float t = __shfl_up_sync(0xffffffffu, incl, o);
            if (lane >= o) incl += t;
        }
        const float excl = incl - p;
        se[2 * lane]     = e2.x;
        se[2 * lane + 1] = e2.y;
        srcp[2 * lane]     = __fdividef(1.f, pe + excl + e2.x);
        srcp[2 * lane + 1] = __fdividef(1.f, pe + incl);
    }
    __syncthreads();

    // exclusive EV start: chunk prefix (8 smem) + ONE g_sub load
    float accEV = g_sub[(blk * NSUB + sub) * E_ + d];
    #pragma unroll
    for (int s = 0; s < NSUB; s++) accEV += sqEV[s * E_ + d];

    // inclusive scan over 8 rows; V direct from L2; divide-free output
    const float* v = values + base + r0 * HE_ + d;
    float*       o = out    + base + r0 * HE_ + d;
    #pragma unroll
    for (int r = 0; r < RPS; r++) {
        accEV = fmaf(se[r0 + r], v[r * HE_], accEV);
        o[r * HE_] = accEV * srcp[r0 + r];
    }
}

extern "C" void kernel_launch(void* const* d_in, const int* in_sizes, int n_in,
                              void* d_out, int out_size) {
    // inputs: 0=queries (unused: a_q cancels in softmax), 1=keys, 2=values,
    //         3=w_score, 4=b_score (unused: cancels)
    const float* keys   = (const float*)d_in[1];
    const float* values = (const float*)d_in[2];
    const float* w      = (const float*)d_in[3];
    float* out = (float*)d_out;

    k_aggregate<<<NBLK, NT_>>>(keys, values, w);
    k_output<<<NBLK, NT_>>>(values, out);
}